// round 3
// baseline (speedup 1.0000x reference)
#include <cuda_runtime.h>
#include <math.h>

#define NIMG 16
#define CDIM 1024
#define PDIM 1024
#define KCL  32
#define EPSN 1e-12f

// scratch (no allocations allowed)
__device__ float g_a[NIMG * KCL * PDIM];   // softmax weights a[n][k][p]
__device__ float g_r[NIMG * PDIM];         // per-pixel inverse L2 norm
__device__ float g_asum[NIMG * KCL];       // sum_p a[n][k][p]
__device__ float g_gn[NIMG];               // global sumsq per image

// ---------------- kernel Z: zero accumulators ----------------
__global__ void kz() {
    int t = blockIdx.x * blockDim.x + threadIdx.x;
    if (t < NIMG * KCL) g_asum[t] = 0.f;
    if (t < NIMG) g_gn[t] = 0.f;
}

// ---------------- kernel A: per (n, 128-pixel tile) ----------------
// computes per-pixel inverse norm r, logits = r * (w . x), softmax over k,
// stores a to g_a, r to g_r, accumulates asum.
__global__ void __launch_bounds__(256) ka(const float* __restrict__ x,
                                          const float* __restrict__ w) {
    __shared__ float xs[32][129];   // [c-chunk][px]  (reused as logits L[k][px])
    __shared__ float ws[32][33];    // [k][c-chunk]
    __shared__ float rs[128];
    __shared__ float asum_s[KCL];

    const int n = blockIdx.y;
    const int pbase = blockIdx.x * 128;
    const int tid = threadIdx.x;
    const int kg = tid >> 5;    // 0..7  (k = kg + 8*j)
    const int pg = tid & 31;    // 0..31 (px = pg + 32*jj)

    float acc[4][4];
#pragma unroll
    for (int j = 0; j < 4; j++)
#pragma unroll
        for (int jj = 0; jj < 4; jj++) acc[j][jj] = 0.f;
    float ssq[4] = {0.f, 0.f, 0.f, 0.f};

    const float* xn = x + (size_t)n * CDIM * PDIM + pbase;

    for (int cc = 0; cc < CDIM; cc += 32) {
        // load x chunk: 32 c x 128 px, coalesced over p
#pragma unroll
        for (int i = 0; i < 16; i++) {
            int idx = tid + i * 256;
            int c = idx >> 7, p = idx & 127;
            xs[c][p] = xn[(size_t)(cc + c) * PDIM + p];
        }
        // load w chunk: 32 k x 32 c, coalesced over c
#pragma unroll
        for (int i = 0; i < 4; i++) {
            int idx = tid + i * 256;
            int k = idx >> 5, c = idx & 31;
            ws[k][c] = w[k * CDIM + cc + c];
        }
        __syncthreads();
#pragma unroll
        for (int c = 0; c < 32; c++) {
            float wv[4], xv[4];
#pragma unroll
            for (int j = 0; j < 4; j++) wv[j] = ws[kg + 8 * j][c];
#pragma unroll
            for (int jj = 0; jj < 4; jj++) xv[jj] = xs[c][pg + 32 * jj];
#pragma unroll
            for (int j = 0; j < 4; j++)
#pragma unroll
                for (int jj = 0; jj < 4; jj++) acc[j][jj] += wv[j] * xv[jj];
            if (kg == 0) {  // warp 0 computes per-pixel sumsq
#pragma unroll
                for (int jj = 0; jj < 4; jj++) ssq[jj] += xv[jj] * xv[jj];
            }
        }
        __syncthreads();
    }

    // warp 0: inverse norms
    if (kg == 0) {
#pragma unroll
        for (int jj = 0; jj < 4; jj++) {
            float r = 1.f / fmaxf(sqrtf(ssq[jj]), EPSN);
            rs[pg + 32 * jj] = r;
            g_r[n * PDIM + pbase + pg + 32 * jj] = r;
        }
    }
    if (tid < KCL) asum_s[tid] = 0.f;
    __syncthreads();

    // logits (scaled by r) into smem, reusing xs as L[k][px]
#pragma unroll
    for (int j = 0; j < 4; j++)
#pragma unroll
        for (int jj = 0; jj < 4; jj++)
            xs[kg + 8 * j][pg + 32 * jj] = acc[j][jj] * rs[pg + 32 * jj];
    __syncthreads();

    // softmax over k: one pixel per thread (threads 0..127)
    if (tid < 128) {
        const int px = tid;
        const int lane = tid & 31;
        float m = -INFINITY;
#pragma unroll
        for (int k = 0; k < KCL; k++) m = fmaxf(m, xs[k][px]);
        float e[KCL];
        float s = 0.f;
#pragma unroll
        for (int k = 0; k < KCL; k++) {
            e[k] = __expf(xs[k][px] - m);
            s += e[k];
        }
        float inv = 1.f / s;
#pragma unroll
        for (int k = 0; k < KCL; k++) {
            float a = e[k] * inv;
            g_a[((size_t)n * KCL + k) * PDIM + pbase + px] = a;
            // warp-reduce partial asum over the 32 pixels of this warp
            float v = a;
            v += __shfl_xor_sync(0xffffffffu, v, 16);
            v += __shfl_xor_sync(0xffffffffu, v, 8);
            v += __shfl_xor_sync(0xffffffffu, v, 4);
            v += __shfl_xor_sync(0xffffffffu, v, 2);
            v += __shfl_xor_sync(0xffffffffu, v, 1);
            if (lane == 0) atomicAdd(&asum_s[k], v);
        }
    }
    __syncthreads();
    if (tid < KCL) atomicAdd(&g_asum[n * KCL + tid], asum_s[tid]);
}

// ---------------- kernel B: vlad GEMM ----------------
// vlad[n][k][c] = sum_p a[n][k][p] * x[n][c][p] * r[n][p]  -  asum[n][k]*cent[k][c]
__global__ void __launch_bounds__(256) kb(const float* __restrict__ x,
                                          const float* __restrict__ cent,
                                          float* __restrict__ out) {
    __shared__ float as_[32][33];   // [k][pp]
    __shared__ float xs[128][33];   // [c][pp]

    const int n = blockIdx.y;
    const int cbase = blockIdx.x * 128;
    const int tid = threadIdx.x;
    const int kg = tid >> 5;   // k = kg + 8*j
    const int cg = tid & 31;   // c = cbase + cg + 32*jj

    float acc[4][4];
#pragma unroll
    for (int j = 0; j < 4; j++)
#pragma unroll
        for (int jj = 0; jj < 4; jj++) acc[j][jj] = 0.f;

    const float* xn = x + (size_t)n * CDIM * PDIM + (size_t)cbase * PDIM;
    const float* an = g_a + (size_t)n * KCL * PDIM;
    const float* rn = g_r + n * PDIM;

    for (int pc = 0; pc < PDIM; pc += 32) {
#pragma unroll
        for (int i = 0; i < 4; i++) {
            int idx = tid + i * 256;
            int k = idx >> 5, pp = idx & 31;
            as_[k][pp] = an[(size_t)k * PDIM + pc + pp];
        }
#pragma unroll
        for (int i = 0; i < 16; i++) {
            int idx = tid + i * 256;
            int c = idx >> 5, pp = idx & 31;
            xs[c][pp] = xn[(size_t)c * PDIM + pc + pp] * rn[pc + pp];
        }
        __syncthreads();
#pragma unroll
        for (int pp = 0; pp < 32; pp++) {
            float av[4], xv[4];
#pragma unroll
            for (int j = 0; j < 4; j++) av[j] = as_[kg + 8 * j][pp];
#pragma unroll
            for (int jj = 0; jj < 4; jj++) xv[jj] = xs[cg + 32 * jj][pp];
#pragma unroll
            for (int j = 0; j < 4; j++)
#pragma unroll
                for (int jj = 0; jj < 4; jj++) acc[j][jj] += av[j] * xv[jj];
        }
        __syncthreads();
    }

#pragma unroll
    for (int j = 0; j < 4; j++) {
        int k = kg + 8 * j;
        float asum = g_asum[n * KCL + k];
#pragma unroll
        for (int jj = 0; jj < 4; jj++) {
            int c = cbase + cg + 32 * jj;
            out[((size_t)n * KCL + k) * CDIM + c] =
                acc[j][jj] - asum * cent[k * CDIM + c];
        }
    }
}

// ---------------- kernel C: intra-cluster L2 normalize + global sumsq ----------------
__global__ void __launch_bounds__(256) kc(float* __restrict__ out) {
    const int row = blockIdx.x;        // n*K + k
    const int n = row >> 5;
    float* p = out + (size_t)row * CDIM;
    const int tid = threadIdx.x;

    float s = 0.f;
#pragma unroll
    for (int i = tid; i < CDIM; i += 256) {
        float v = p[i];
        s += v * v;
    }
    // block reduce (8 warps)
    __shared__ float sh[8];
    int lane = tid & 31, wid = tid >> 5;
    s += __shfl_xor_sync(0xffffffffu, s, 16);
    s += __shfl_xor_sync(0xffffffffu, s, 8);
    s += __shfl_xor_sync(0xffffffffu, s, 4);
    s += __shfl_xor_sync(0xffffffffu, s, 2);
    s += __shfl_xor_sync(0xffffffffu, s, 1);
    if (lane == 0) sh[wid] = s;
    __syncthreads();
    __shared__ float inv_s;
    if (tid == 0) {
        float tot = 0.f;
#pragma unroll
        for (int i = 0; i < 8; i++) tot += sh[i];
        float inv = 1.f / fmaxf(sqrtf(tot), EPSN);
        inv_s = inv;
        atomicAdd(&g_gn[n], tot * inv * inv);
    }
    __syncthreads();
    float inv = inv_s;
#pragma unroll
    for (int i = tid; i < CDIM; i += 256) p[i] *= inv;
}

// ---------------- kernel D: global L2 normalize ----------------
__global__ void __launch_bounds__(256) kd(float* __restrict__ out) {
    int i = blockIdx.x * 256 + threadIdx.x;   // over N*K*C = 524288
    int n = i >> 15;                          // K*C = 32768
    float inv = 1.f / fmaxf(sqrtf(g_gn[n]), EPSN);
    out[i] *= inv;
}

extern "C" void kernel_launch(void* const* d_in, const int* in_sizes, int n_in,
                              void* d_out, int out_size) {
    const float* x = (const float*)d_in[0];       // (16,1024,32,32)
    const float* w = (const float*)d_in[1];       // (32,1024)
    const float* cent = (const float*)d_in[2];    // (32,1024)
    float* out = (float*)d_out;                   // (16, 32768)

    kz<<<2, 256>>>();
    ka<<<dim3(PDIM / 128, NIMG), 256>>>(x, w);
    kb<<<dim3(CDIM / 128, NIMG), 256>>>(x, cent, out);
    kc<<<NIMG * KCL, 256>>>(out);
    kd<<<(NIMG * KCL * CDIM) / 256, 256>>>(out);
}

// round 4
// speedup vs baseline: 1.7841x; 1.7841x over previous
#include <cuda_runtime.h>
#include <math.h>

#define NI 16
#define CD 1024
#define PD 1024
#define KC 32
#define EPSN 1e-12f

typedef unsigned long long u64;

// ---- scratch (static __device__; no allocations allowed) ----
__device__ float g_lp[8 * NI * KC * PD];   // logits partials per c-slice (16MB)
__device__ float g_sp[8 * NI * PD];        // ssq partials (512KB)
__device__ float g_ar[NI * KC * PD];       // a * r (2MB)
__device__ float g_asp[NI * KC * 32];      // asum warp partials
__device__ float g_asum[NI * KC];
__device__ float g_vp[8 * NI * KC * CD];   // vlad partials (16MB)
__device__ float g_gg[NI * KC];            // per-row scaled sumsq

__device__ __forceinline__ void ffma2(u64 &d, u64 a, u64 b) {
    asm("fma.rn.f32x2 %0, %1, %2, %0;" : "+l"(d) : "l"(a), "l"(b));
}
__device__ __forceinline__ float2 unpk(u64 v) {
    float2 r; asm("mov.b64 {%0, %1}, %2;" : "=f"(r.x), "=f"(r.y) : "l"(v)); return r;
}

#define CPA16(d, s) asm volatile("cp.async.cg.shared.global [%0], [%1], 16;" :: "r"(d), "l"(s))
#define CPA8(d, s)  asm volatile("cp.async.ca.shared.global [%0], [%1], 8;"  :: "r"(d), "l"(s))
#define CPC()  asm volatile("cp.async.commit_group;")
#define CPW1() asm volatile("cp.async.wait_group 1;")
#define CPW0() asm volatile("cp.async.wait_group 0;")

// =======================================================================
// Kernel A: logits partial GEMM.  Block = 32k x 256px, 128c-slice.
// grid (32, 16): bx = pt*8 + cs.  128 threads; thread tile 8k x 8px (f32x2 over px).
// Also accumulates per-pixel sum-of-squares (warp 0).
// =======================================================================
#define KA_SMEM (2 * 32 * 256 * 4 + 128 * 33 * 8)

__global__ void __launch_bounds__(128, 2) ka(const float* __restrict__ x,
                                             const float* __restrict__ w) {
    extern __shared__ float sm[];
    float* xs = sm;                              // [2][32][256]
    float2* ws2 = (float2*)(sm + 2 * 32 * 256);  // [128][33] duplicated pairs
    const int tid = threadIdx.x, lane = tid & 31, wp = tid >> 5;
    const int pt = blockIdx.x >> 3, cs = blockIdx.x & 7, n = blockIdx.y;
    const int pbase = pt * 256, cbase = cs * 128;
    const unsigned sb = (unsigned)__cvta_generic_to_shared(sm);

    // w slice -> smem, transposed + duplicated: ws2[c][k] = {w,w}
#pragma unroll
    for (int j = 0; j < 32; j++) {
        float v = w[j * CD + cbase + tid];
        ws2[tid * 33 + j] = make_float2(v, v);
    }

    const float* xb = x + ((size_t)n * CD + cbase) * PD + pbase;

    // prefetch chunk 0
#pragma unroll
    for (int i = 0; i < 16; i++) {
        int slot = tid + i * 128;
        int c = slot >> 6, p4 = (slot & 63) << 2;
        CPA16(sb + (unsigned)((c << 8) + p4) * 4u, xb + (size_t)c * PD + p4);
    }
    CPC();

    u64 acc[8][4];
#pragma unroll
    for (int j = 0; j < 8; j++)
#pragma unroll
        for (int q = 0; q < 4; q++) acc[j][q] = 0ull;
    u64 ssq[4] = {0ull, 0ull, 0ull, 0ull};

    for (int ch = 0; ch < 4; ch++) {
        const int buf = ch & 1;
        if (ch < 3) {
            const float* s0 = xb + (size_t)(ch + 1) * 32 * PD;
            const unsigned d0 = sb + (unsigned)(buf ^ 1) * 32768u;
#pragma unroll
            for (int i = 0; i < 16; i++) {
                int slot = tid + i * 128;
                int c = slot >> 6, p4 = (slot & 63) << 2;
                CPA16(d0 + (unsigned)((c << 8) + p4) * 4u, s0 + (size_t)c * PD + p4);
            }
            CPC();
            CPW1();
        } else {
            CPW0();
        }
        __syncthreads();
        const float* xchunk = xs + buf * 8192;
        const float2* wch = ws2 + (ch * 32) * 33;
#pragma unroll 4
        for (int c = 0; c < 32; c++) {
            const u64* wr = (const u64*)(wch + c * 33 + wp * 8);
            u64 wv[8];
#pragma unroll
            for (int j = 0; j < 8; j++) wv[j] = wr[j];
            const float* xrow = xchunk + c * 256;
            ulonglong2 X0 = *(const ulonglong2*)(xrow + lane * 4);
            ulonglong2 X1 = *(const ulonglong2*)(xrow + 128 + lane * 4);
            u64 xv[4] = {X0.x, X0.y, X1.x, X1.y};
#pragma unroll
            for (int j = 0; j < 8; j++)
#pragma unroll
                for (int q = 0; q < 4; q++) ffma2(acc[j][q], wv[j], xv[q]);
            if (wp == 0) {
#pragma unroll
                for (int q = 0; q < 4; q++) ffma2(ssq[q], xv[q], xv[q]);
            }
        }
        __syncthreads();
    }

    // epilogue: store logit partials
#pragma unroll
    for (int j = 0; j < 8; j++) {
        int k = wp * 8 + j;
        float* bp = g_lp + (((size_t)cs * NI + n) * KC + k) * PD + pbase;
        float2 a0 = unpk(acc[j][0]), a1 = unpk(acc[j][1]);
        *(float4*)(bp + lane * 4) = make_float4(a0.x, a0.y, a1.x, a1.y);
        float2 a2_ = unpk(acc[j][2]), a3_ = unpk(acc[j][3]);
        *(float4*)(bp + 128 + lane * 4) = make_float4(a2_.x, a2_.y, a3_.x, a3_.y);
    }
    if (wp == 0) {
        float* sp = g_sp + ((size_t)cs * NI + n) * PD + pbase;
        float2 s0 = unpk(ssq[0]), s1 = unpk(ssq[1]);
        *(float4*)(sp + lane * 4) = make_float4(s0.x, s0.y, s1.x, s1.y);
        float2 s2 = unpk(ssq[2]), s3 = unpk(ssq[3]);
        *(float4*)(sp + 128 + lane * 4) = make_float4(s2.x, s2.y, s3.x, s3.y);
    }
}

// =======================================================================
// Kernel A2: reduce partials, r = 1/max(||x||,eps), softmax, store a*r, asum partials.
// grid (8, 16), 128 threads, 1 px/thread.
// =======================================================================
__global__ void __launch_bounds__(128) a2k() {
    const int pc = blockIdx.x, n = blockIdx.y, tid = threadIdx.x;
    const int px = pc * 128 + tid;
    float ssq = 0.f;
#pragma unroll
    for (int cs = 0; cs < 8; cs++) ssq += g_sp[((size_t)cs * NI + n) * PD + px];
    float r = 1.f / fmaxf(sqrtf(ssq), EPSN);
    float L[KC];
    float m = -1e30f;
#pragma unroll
    for (int k = 0; k < KC; k++) {
        float s = 0.f;
#pragma unroll
        for (int cs = 0; cs < 8; cs++) s += g_lp[(((size_t)cs * NI + n) * KC + k) * PD + px];
        s *= r;
        L[k] = s;
        m = fmaxf(m, s);
    }
    float sum = 0.f;
#pragma unroll
    for (int k = 0; k < KC; k++) { L[k] = __expf(L[k] - m); sum += L[k]; }
    float inv = 1.f / sum;
    const int lane = tid & 31, wp = tid >> 5;
#pragma unroll
    for (int k = 0; k < KC; k++) {
        float a = L[k] * inv;
        g_ar[((size_t)n * KC + k) * PD + px] = a * r;
        float v = a;
        v += __shfl_xor_sync(0xffffffffu, v, 16);
        v += __shfl_xor_sync(0xffffffffu, v, 8);
        v += __shfl_xor_sync(0xffffffffu, v, 4);
        v += __shfl_xor_sync(0xffffffffu, v, 2);
        v += __shfl_xor_sync(0xffffffffu, v, 1);
        if (lane == 0) g_asp[(n * KC + k) * 32 + pc * 4 + wp] = v;
    }
}

// Kernel A3: deterministic asum reduce. 1 block, 512 threads.
__global__ void a3k() {
    int t = threadIdx.x;
    float s = 0.f;
#pragma unroll
    for (int i = 0; i < 32; i++) s += g_asp[t * 32 + i];
    g_asum[t] = s;
}

// =======================================================================
// Kernel B: vlad partial GEMM.  Block = 32k x 128c, 128p-slice.
// grid (64, 16): bx = ct*8 + ps.  128 threads; thread tile 8k x 4c, f32x2 over p.
// =======================================================================
#define KB_XSZ (128 * 34)
#define KB_SMEM ((2 * KB_XSZ + 32 * 132) * 4)

__global__ void __launch_bounds__(128, 4) kb(const float* __restrict__ x) {
    extern __shared__ float sm[];
    float* xs = sm;                   // [2][128][34]
    float* as_ = sm + 2 * KB_XSZ;     // [32][132]
    const int tid = threadIdx.x, lane = tid & 31, wp = tid >> 5;
    const int ct = blockIdx.x >> 3, ps = blockIdx.x & 7, n = blockIdx.y;
    const int cbase = ct * 128, pbase = ps * 128;
    const unsigned sb = (unsigned)__cvta_generic_to_shared(sm);
    const unsigned sxb = sb;

#pragma unroll
    for (int j = 0; j < 32; j++)
        as_[j * 132 + tid] = g_ar[((size_t)n * KC + j) * PD + pbase + tid];

    const float* xb = x + ((size_t)n * CD + cbase) * PD + pbase;

    // prefetch chunk 0
#pragma unroll
    for (int i = 0; i < 16; i++) {
        int slot = tid + i * 128;
        int c = slot >> 4, p2 = (slot & 15) << 1;
        CPA8(sxb + (unsigned)(c * 34 + p2) * 4u, xb + (size_t)c * PD + p2);
    }
    CPC();

    u64 acc[8][4];
#pragma unroll
    for (int j = 0; j < 8; j++)
#pragma unroll
        for (int u = 0; u < 4; u++) acc[j][u] = 0ull;

    for (int ch = 0; ch < 4; ch++) {
        const int buf = ch & 1;
        if (ch < 3) {
            const unsigned d0 = sxb + (unsigned)(buf ^ 1) * (KB_XSZ * 4u);
            const int poff = (ch + 1) * 32;
#pragma unroll
            for (int i = 0; i < 16; i++) {
                int slot = tid + i * 128;
                int c = slot >> 4, p2 = (slot & 15) << 1;
                CPA8(d0 + (unsigned)(c * 34 + p2) * 4u, xb + (size_t)c * PD + poff + p2);
            }
            CPC();
            CPW1();
        } else {
            CPW0();
        }
        __syncthreads();
        const float* xc = xs + buf * KB_XSZ;
        const float* ac = as_ + ch * 32;
#pragma unroll 4
        for (int t = 0; t < 16; t++) {
            u64 av[8];
#pragma unroll
            for (int j = 0; j < 8; j++) av[j] = *(const u64*)(ac + (wp * 8 + j) * 132 + 2 * t);
            u64 xv[4];
#pragma unroll
            for (int u = 0; u < 4; u++) xv[u] = *(const u64*)(xc + (lane + 32 * u) * 34 + 2 * t);
#pragma unroll
            for (int j = 0; j < 8; j++)
#pragma unroll
                for (int u = 0; u < 4; u++) ffma2(acc[j][u], av[j], xv[u]);
        }
        __syncthreads();
    }

#pragma unroll
    for (int j = 0; j < 8; j++) {
        int k = wp * 8 + j;
        float* vp = g_vp + (((size_t)ps * NI + n) * KC + k) * CD + cbase;
#pragma unroll
        for (int u = 0; u < 4; u++) {
            float2 pr = unpk(acc[j][u]);
            vp[lane + 32 * u] = pr.x + pr.y;
        }
    }
}

// =======================================================================
// Kernel C2: reduce vlad partials, subtract asum*centroid, row L2 norm.
// grid 512 (row = n*32+k), 256 threads, 4c each.
// =======================================================================
__global__ void __launch_bounds__(256) kc2(const float* __restrict__ cent,
                                           float* __restrict__ out) {
    const int row = blockIdx.x, n = row >> 5, k = row & 31;
    const int tid = threadIdx.x, lane = tid & 31, wp = tid >> 5;
    const int c = tid * 4;
    float4 v = make_float4(0.f, 0.f, 0.f, 0.f);
#pragma unroll
    for (int ps = 0; ps < 8; ps++) {
        float4 q = *(const float4*)(g_vp + (((size_t)ps * NI + n) * KC + k) * CD + c);
        v.x += q.x; v.y += q.y; v.z += q.z; v.w += q.w;
    }
    float asum = g_asum[n * KC + k];
    float4 ce = *(const float4*)(cent + k * CD + c);
    v.x -= asum * ce.x; v.y -= asum * ce.y; v.z -= asum * ce.z; v.w -= asum * ce.w;
    float s = v.x * v.x + v.y * v.y + v.z * v.z + v.w * v.w;
    __shared__ float sh[8];
    __shared__ float sinv;
    s += __shfl_xor_sync(0xffffffffu, s, 16);
    s += __shfl_xor_sync(0xffffffffu, s, 8);
    s += __shfl_xor_sync(0xffffffffu, s, 4);
    s += __shfl_xor_sync(0xffffffffu, s, 2);
    s += __shfl_xor_sync(0xffffffffu, s, 1);
    if (lane == 0) sh[wp] = s;
    __syncthreads();
    if (tid == 0) {
        float tot = 0.f;
#pragma unroll
        for (int i = 0; i < 8; i++) tot += sh[i];
        float inv = 1.f / fmaxf(sqrtf(tot), EPSN);
        sinv = inv;
        g_gg[row] = tot * inv * inv;
    }
    __syncthreads();
    float inv = sinv;
    *(float4*)(out + (size_t)row * CD + c) =
        make_float4(v.x * inv, v.y * inv, v.z * inv, v.w * inv);
}

// Kernel D: global L2 normalize. grid 512 rows, 256 threads (4 floats each).
__global__ void __launch_bounds__(256) kd(float* __restrict__ out) {
    const int row = blockIdx.x, n = row >> 5, tid = threadIdx.x;
    __shared__ float sinv;
    if (tid < 32) {
        float v = g_gg[n * 32 + tid];
        v += __shfl_xor_sync(0xffffffffu, v, 16);
        v += __shfl_xor_sync(0xffffffffu, v, 8);
        v += __shfl_xor_sync(0xffffffffu, v, 4);
        v += __shfl_xor_sync(0xffffffffu, v, 2);
        v += __shfl_xor_sync(0xffffffffu, v, 1);
        if (tid == 0) sinv = 1.f / fmaxf(sqrtf(v), EPSN);
    }
    __syncthreads();
    float inv = sinv;
    float4* p = (float4*)(out + (size_t)row * CD) + tid;
    float4 v = *p;
    *p = make_float4(v.x * inv, v.y * inv, v.z * inv, v.w * inv);
}

extern "C" void kernel_launch(void* const* d_in, const int* in_sizes, int n_in,
                              void* d_out, int out_size) {
    const float* x = (const float*)d_in[0];     // (16,1024,32,32)
    const float* w = (const float*)d_in[1];     // (32,1024)
    const float* cent = (const float*)d_in[2];  // (32,1024)
    float* out = (float*)d_out;                 // (16, 32768)

    cudaFuncSetAttribute(ka, cudaFuncAttributeMaxDynamicSharedMemorySize, KA_SMEM);
    cudaFuncSetAttribute(kb, cudaFuncAttributeMaxDynamicSharedMemorySize, KB_SMEM);

    ka<<<dim3(32, 16), 128, KA_SMEM>>>(x, w);
    a2k<<<dim3(8, 16), 128>>>();
    a3k<<<1, 512>>>();
    kb<<<dim3(64, 16), 128, KB_SMEM>>>(x);
    kc2<<<512, 256>>>(cent, out);
    kd<<<512, 256>>>(out);
}

// round 8
// speedup vs baseline: 3.4681x; 1.9439x over previous
#include <cuda_runtime.h>
#include <math.h>
#include <stdint.h>

#define NI 16
#define CD 1024
#define PD 1024
#define KC 32
#define EPSN 1e-12f

// ---- scratch (static; no allocations allowed) ----
__device__ float g_ar[NI * KC * PD];     // softmax(a)*r  (kb's B operand)
__device__ float g_asp[NI * KC * 32];    // asum partials (ptile x warp)
__device__ float g_asum[NI * KC];
__device__ float g_v[NI * KC * CD];      // raw vlad gemm D
__device__ float g_gg[NI * KC];

__device__ __forceinline__ uint32_t s2u(const void* p) {
    uint32_t a;
    asm("{ .reg .u64 t; cvta.to.shared.u64 t, %1; cvt.u32.u64 %0, t; }" : "=r"(a) : "l"(p));
    return a;
}

#define CPA16(d, s) asm volatile("cp.async.cg.shared.global [%0], [%1], 16;" :: "r"(d), "l"(s))
#define CPC()  asm volatile("cp.async.commit_group;")
#define CPW1() asm volatile("cp.async.wait_group 1;")
#define CPW0() asm volatile("cp.async.wait_group 0;")

// tf32 m16n8k8 row.col: D += A*B  (A: 4 regs, B: 2 regs, D: 4 floats)
__device__ __forceinline__ void mma8(float* d, const uint32_t* a, const uint32_t* b) {
    asm volatile(
        "mma.sync.aligned.m16n8k8.row.col.f32.tf32.tf32.f32 "
        "{%0,%1,%2,%3}, {%4,%5,%6,%7}, {%8,%9}, {%0,%1,%2,%3};"
        : "+f"(d[0]), "+f"(d[1]), "+f"(d[2]), "+f"(d[3])
        : "r"(a[0]), "r"(a[1]), "r"(a[2]), "r"(a[3]), "r"(b[0]), "r"(b[1]));
}

// =====================================================================
// ka: logits GEMM + per-pixel norm + softmax, fused.
//   D[k=32, p=128] = sum_c w[k,c] * x[c,p]   (m=k, n=p, red=c)
//   grid (8 ptiles, 16 n), 128 threads (4 warps).
//   warp: 2 m16 x 4 n8 tiles (all k, 32 px).
// =====================================================================
__global__ void __launch_bounds__(128, 1) ka(const float* __restrict__ x,
                                             const float* __restrict__ w) {
    __shared__ float xs[2][32][136];   // [buf][c][px]   stride 136 (mod32=8)
    __shared__ float ws[2][32][36];    // [buf][k][c]    stride 36  (mod32=4)
    const int tid = threadIdx.x;
    const int lane = tid & 31, wp = tid >> 5;
    const int qid = lane >> 2, qlane = lane & 3;
    const int ptile = blockIdx.x, n = blockIdx.y, pbase = ptile * 128;
    const float* xn = x + (size_t)n * CD * PD + pbase;

    const uint32_t xsu = s2u(&xs[0][0][0]);
    const uint32_t wsu = s2u(&ws[0][0][0]);

    float d[2][4][4];
#pragma unroll
    for (int mi = 0; mi < 2; mi++)
#pragma unroll
        for (int ni = 0; ni < 4; ni++)
#pragma unroll
            for (int r = 0; r < 4; r++) d[mi][ni][r] = 0.f;
    float ssq = 0.f;

#define KA_LD(ch, buf) do { \
        const float* _x = xn + (size_t)(ch) * 32 * PD; \
        uint32_t _xd = xsu + (buf) * (32 * 136 * 4); \
        _Pragma("unroll") \
        for (int i = 0; i < 8; i++) { \
            int idx = tid + i * 128, c = idx >> 5, p4 = idx & 31; \
            CPA16(_xd + (unsigned)(c * 136 + p4 * 4) * 4u, _x + (size_t)c * PD + p4 * 4); \
        } \
        const float* _w = w + (ch) * 32; \
        uint32_t _wd = wsu + (buf) * (32 * 36 * 4); \
        _Pragma("unroll") \
        for (int i = 0; i < 2; i++) { \
            int idx = tid + i * 128, k = idx >> 3, c4 = idx & 7; \
            CPA16(_wd + (unsigned)(k * 36 + c4 * 4) * 4u, _w + (size_t)k * CD + c4 * 4); \
        } \
        CPC(); \
    } while (0)

    KA_LD(0, 0);
    KA_LD(1, 1);

    for (int ch = 0; ch < 32; ch++) {
        const int buf = ch & 1;
        if (ch < 31) CPW1(); else CPW0();
        __syncthreads();
        // per-pixel sum of squares (thread owns pixel = tid)
#pragma unroll
        for (int c = 0; c < 32; c++) {
            float f = xs[buf][c][tid];
            ssq = fmaf(f, f, ssq);
        }
#pragma unroll
        for (int s = 0; s < 4; s++) {
            uint32_t a[2][4], b[4][2];
            const int c0 = s * 8 + qlane;
#pragma unroll
            for (int mi = 0; mi < 2; mi++) {
                const int r0 = mi * 16 + qid;
                a[mi][0] = __float_as_uint(ws[buf][r0][c0]);
                a[mi][1] = __float_as_uint(ws[buf][r0 + 8][c0]);
                a[mi][2] = __float_as_uint(ws[buf][r0][c0 + 4]);
                a[mi][3] = __float_as_uint(ws[buf][r0 + 8][c0 + 4]);
            }
#pragma unroll
            for (int ni = 0; ni < 4; ni++) {
                const int pc = wp * 32 + ni * 8 + qid;
                b[ni][0] = __float_as_uint(xs[buf][c0][pc]);
                b[ni][1] = __float_as_uint(xs[buf][c0 + 4][pc]);
            }
#pragma unroll
            for (int mi = 0; mi < 2; mi++)
#pragma unroll
                for (int ni = 0; ni < 4; ni++) mma8(d[mi][ni], a[mi], b[ni]);
        }
        __syncthreads();
        if (ch + 2 < 32) KA_LD(ch + 2, buf);
    }
#undef KA_LD

    // ---- store logits to smem (reuse xs[0]: [32 k][136]) ----
    float (*Ls)[136] = xs[0];
#pragma unroll
    for (int mi = 0; mi < 2; mi++)
#pragma unroll
        for (int ni = 0; ni < 4; ni++) {
            const int px = wp * 32 + ni * 8 + 2 * qlane;
            *(float2*)&Ls[mi * 16 + qid][px] = make_float2(d[mi][ni][0], d[mi][ni][1]);
            *(float2*)&Ls[mi * 16 + qid + 8][px] = make_float2(d[mi][ni][2], d[mi][ni][3]);
        }
    __syncthreads();

    // ---- softmax: thread owns pixel tid ----
    const float r = 1.f / fmaxf(sqrtf(ssq), EPSN);
    float L[KC], m = -1e30f;
#pragma unroll
    for (int k = 0; k < KC; k++) {
        L[k] = Ls[k][tid] * r;
        m = fmaxf(m, L[k]);
    }
    float ssum = 0.f;
#pragma unroll
    for (int k = 0; k < KC; k++) {
        L[k] = __expf(L[k] - m);
        ssum += L[k];
    }
    const float inv = 1.f / ssum;
    float* arp = g_ar + (size_t)n * KC * PD + pbase + tid;
#pragma unroll
    for (int k = 0; k < KC; k++) {
        float a = L[k] * inv;
        arp[(size_t)k * PD] = a * r;
        float t = a;
        t += __shfl_xor_sync(0xffffffffu, t, 16);
        t += __shfl_xor_sync(0xffffffffu, t, 8);
        t += __shfl_xor_sync(0xffffffffu, t, 4);
        t += __shfl_xor_sync(0xffffffffu, t, 2);
        t += __shfl_xor_sync(0xffffffffu, t, 1);
        if (lane == 0) g_asp[(n * KC + k) * 32 + ptile * 4 + wp] = t;
    }
}

// asum reduce (deterministic). 1 block, 512 threads.
__global__ void a3k() {
    int t = threadIdx.x;
    float s = 0.f;
#pragma unroll
    for (int i = 0; i < 32; i++) s += g_asp[t * 32 + i];
    g_asum[t] = s;
}

// =====================================================================
// kb: vlad GEMM.
//   D[c=128, k=32] = sum_p x[c,p] * ar[k,p]   (m=c, n=k, red=p)
//   grid (8 ctiles, 16 n), 128 threads (4 warps).
//   warp: 2 m16 (32 c) x 4 n8 (all k).
// =====================================================================
__global__ void __launch_bounds__(128, 1) kb(const float* __restrict__ x) {
    __shared__ float xs[2][128][36];   // [buf][c][p]  stride 36
    __shared__ float as_[2][32][36];   // [buf][k][p]  stride 36
    const int tid = threadIdx.x;
    const int lane = tid & 31, wp = tid >> 5;
    const int qid = lane >> 2, qlane = lane & 3;
    const int ctile = blockIdx.x, n = blockIdx.y, cbase = ctile * 128;
    const float* xn = x + ((size_t)n * CD + cbase) * PD;
    const float* arn = g_ar + (size_t)n * KC * PD;

    const uint32_t xsu = s2u(&xs[0][0][0]);
    const uint32_t asu = s2u(&as_[0][0][0]);

    float d[2][4][4];
#pragma unroll
    for (int mi = 0; mi < 2; mi++)
#pragma unroll
        for (int ni = 0; ni < 4; ni++)
#pragma unroll
            for (int r = 0; r < 4; r++) d[mi][ni][r] = 0.f;

#define KB_LD(ch, buf) do { \
        const int _p0 = (ch) * 32; \
        uint32_t _xd = xsu + (buf) * (128 * 36 * 4); \
        _Pragma("unroll") \
        for (int i = 0; i < 8; i++) { \
            int idx = tid + i * 128, c = idx >> 3, p4 = idx & 7; \
            CPA16(_xd + (unsigned)(c * 36 + p4 * 4) * 4u, xn + (size_t)c * PD + _p0 + p4 * 4); \
        } \
        uint32_t _ad = asu + (buf) * (32 * 36 * 4); \
        _Pragma("unroll") \
        for (int i = 0; i < 2; i++) { \
            int idx = tid + i * 128, k = idx >> 3, p4 = idx & 7; \
            CPA16(_ad + (unsigned)(k * 36 + p4 * 4) * 4u, arn + (size_t)k * PD + _p0 + p4 * 4); \
        } \
        CPC(); \
    } while (0)

    KB_LD(0, 0);
    KB_LD(1, 1);

    for (int ch = 0; ch < 32; ch++) {
        const int buf = ch & 1;
        if (ch < 31) CPW1(); else CPW0();
        __syncthreads();
#pragma unroll
        for (int s = 0; s < 4; s++) {
            uint32_t a[2][4], b[4][2];
            const int p0 = s * 8 + qlane;
#pragma unroll
            for (int mi = 0; mi < 2; mi++) {
                const int r0 = wp * 32 + mi * 16 + qid;
                a[mi][0] = __float_as_uint(xs[buf][r0][p0]);
                a[mi][1] = __float_as_uint(xs[buf][r0 + 8][p0]);
                a[mi][2] = __float_as_uint(xs[buf][r0][p0 + 4]);
                a[mi][3] = __float_as_uint(xs[buf][r0 + 8][p0 + 4]);
            }
#pragma unroll
            for (int ni = 0; ni < 4; ni++) {
                const int kk = ni * 8 + qid;
                b[ni][0] = __float_as_uint(as_[buf][kk][p0]);
                b[ni][1] = __float_as_uint(as_[buf][kk][p0 + 4]);
            }
#pragma unroll
            for (int mi = 0; mi < 2; mi++)
#pragma unroll
                for (int ni = 0; ni < 4; ni++) mma8(d[mi][ni], a[mi], b[ni]);
        }
        __syncthreads();
        if (ch + 2 < 32) KB_LD(ch + 2, buf);
    }
#undef KB_LD

    // epilogue: D[c, k] -> g_v[n][k][c]
    float* gv = g_v + (size_t)n * KC * CD;
#pragma unroll
    for (int mi = 0; mi < 2; mi++) {
        const int c0 = cbase + wp * 32 + mi * 16 + qid;
#pragma unroll
        for (int ni = 0; ni < 4; ni++) {
            const int k0 = ni * 8 + 2 * qlane;
            gv[(size_t)k0 * CD + c0] = d[mi][ni][0];
            gv[(size_t)(k0 + 1) * CD + c0] = d[mi][ni][1];
            gv[(size_t)k0 * CD + c0 + 8] = d[mi][ni][2];
            gv[(size_t)(k0 + 1) * CD + c0 + 8] = d[mi][ni][3];
        }
    }
}

// =====================================================================
// kc2: subtract asum*centroid, intra-cluster L2 norm. grid 512, 256 thr.
// =====================================================================
__global__ void __launch_bounds__(256) kc2(const float* __restrict__ cent,
                                           float* __restrict__ out) {
    const int row = blockIdx.x, k = row & 31;
    const int tid = threadIdx.x, lane = tid & 31, wp = tid >> 5;
    const int c = tid * 4;
    float4 v = *(const float4*)(g_v + (size_t)row * CD + c);
    float asum = g_asum[row];
    float4 ce = *(const float4*)(cent + k * CD + c);
    v.x -= asum * ce.x; v.y -= asum * ce.y; v.z -= asum * ce.z; v.w -= asum * ce.w;
    float s = v.x * v.x + v.y * v.y + v.z * v.z + v.w * v.w;
    __shared__ float sh[8];
    __shared__ float sinv;
    s += __shfl_xor_sync(0xffffffffu, s, 16);
    s += __shfl_xor_sync(0xffffffffu, s, 8);
    s += __shfl_xor_sync(0xffffffffu, s, 4);
    s += __shfl_xor_sync(0xffffffffu, s, 2);
    s += __shfl_xor_sync(0xffffffffu, s, 1);
    if (lane == 0) sh[wp] = s;
    __syncthreads();
    if (tid == 0) {
        float tot = 0.f;
#pragma unroll
        for (int i = 0; i < 8; i++) tot += sh[i];
        float inv = 1.f / fmaxf(sqrtf(tot), EPSN);
        sinv = inv;
        g_gg[row] = tot * inv * inv;
    }
    __syncthreads();
    float inv = sinv;
    *(float4*)(out + (size_t)row * CD + c) =
        make_float4(v.x * inv, v.y * inv, v.z * inv, v.w * inv);
}

// kd: global L2 normalize. grid 512, 256 thr.
__global__ void __launch_bounds__(256) kd(float* __restrict__ out) {
    const int row = blockIdx.x, n = row >> 5, tid = threadIdx.x;
    __shared__ float sinv;
    if (tid < 32) {
        float v = g_gg[n * 32 + tid];
        v += __shfl_xor_sync(0xffffffffu, v, 16);
        v += __shfl_xor_sync(0xffffffffu, v, 8);
        v += __shfl_xor_sync(0xffffffffu, v, 4);
        v += __shfl_xor_sync(0xffffffffu, v, 2);
        v += __shfl_xor_sync(0xffffffffu, v, 1);
        if (tid == 0) sinv = 1.f / fmaxf(sqrtf(v), EPSN);
    }
    __syncthreads();
    float inv = sinv;
    float4* p = (float4*)(out + (size_t)row * CD) + tid;
    float4 v = *p;
    *p = make_float4(v.x * inv, v.y * inv, v.z * inv, v.w * inv);
}

extern "C" void kernel_launch(void* const* d_in, const int* in_sizes, int n_in,
                              void* d_out, int out_size) {
    const float* x = (const float*)d_in[0];     // (16,1024,32,32)
    const float* w = (const float*)d_in[1];     // (32,1024)
    const float* cent = (const float*)d_in[2];  // (32,1024)
    float* out = (float*)d_out;                 // (16,32768)

    ka<<<dim3(8, 16), 128>>>(x, w);
    a3k<<<1, 512>>>();
    kb<<<dim3(8, 16), 128>>>(x);
    kc2<<<512, 256>>>(cent, out);
    kd<<<512, 256>>>(out);
}

// round 9
// speedup vs baseline: 4.3379x; 1.2508x over previous
#include <cuda_runtime.h>
#include <math.h>
#include <stdint.h>

#define NI 16
#define CD 1024
#define PD 1024
#define KC 32
#define EPSN 1e-12f

// ---- scratch (static; no allocations allowed) ----
__device__ float g_ar[NI * KC * PD];     // softmax(a)*r  (kb's B operand)
__device__ float g_asp[NI * KC * 32];    // asum partials (ptile x warp)
__device__ float g_v[NI * KC * CD];      // raw vlad gemm D
__device__ float g_gg[NI * KC];

__device__ __forceinline__ uint32_t s2u(const void* p) {
    uint32_t a;
    asm("{ .reg .u64 t; cvta.to.shared.u64 t, %1; cvt.u32.u64 %0, t; }" : "=r"(a) : "l"(p));
    return a;
}

#define CPA16(d, s) asm volatile("cp.async.cg.shared.global [%0], [%1], 16;" :: "r"(d), "l"(s))
#define CPC()  asm volatile("cp.async.commit_group;")
#define CPW1() asm volatile("cp.async.wait_group 1;")
#define CPW0() asm volatile("cp.async.wait_group 0;")

// tf32 m16n8k8 row.col: D += A*B  (A: 4 regs, B: 2 regs, D: 4 floats)
__device__ __forceinline__ void mma8(float* d, const uint32_t* a, const uint32_t* b) {
    asm volatile(
        "mma.sync.aligned.m16n8k8.row.col.f32.tf32.tf32.f32 "
        "{%0,%1,%2,%3}, {%4,%5,%6,%7}, {%8,%9}, {%0,%1,%2,%3};"
        : "+f"(d[0]), "+f"(d[1]), "+f"(d[2]), "+f"(d[3])
        : "r"(a[0]), "r"(a[1]), "r"(a[2]), "r"(a[3]), "r"(b[0]), "r"(b[1]));
}

// =====================================================================
// ka: logits GEMM + per-pixel norm + softmax, fused.
//   D[k=32, p=128] = sum_c w[k,c] * x[c,p]
//   grid (8 ptiles, 16 n), 256 threads = 2 warpgroups.
//   wg0 reduces c[0..511], wg1 c[512..1023]; partial D combined in smem.
// =====================================================================
#define KA_XSF 4352              // 32*136 floats per buffer
#define KA_WSF 1152              // 32*36 floats per buffer
#define KA_SMEM ((4 * KA_XSF + 4 * KA_WSF) * 4)

__global__ void __launch_bounds__(256, 1) ka(const float* __restrict__ x,
                                             const float* __restrict__ w) {
    extern __shared__ float sm[];
    // xs[wg][buf] at (wg*2+buf)*KA_XSF ; ws[wg][buf] at 4*KA_XSF + (wg*2+buf)*KA_WSF
    __shared__ float ssqs[128];
    const int tid = threadIdx.x;
    const int wg = tid >> 7, wtid = tid & 127;
    const int lane = tid & 31, wp = wtid >> 5;
    const int qid = lane >> 2, qlane = lane & 3;
    const int ptile = blockIdx.x, n = blockIdx.y, pbase = ptile * 128;
    const float* xn = x + (size_t)n * CD * PD + pbase;
    const uint32_t smu = s2u(sm);

    float d[2][4][4];
#pragma unroll
    for (int mi = 0; mi < 2; mi++)
#pragma unroll
        for (int ni = 0; ni < 4; ni++)
#pragma unroll
            for (int r = 0; r < 4; r++) d[mi][ni][r] = 0.f;
    float ssq = 0.f;

#define KA_LD(gch, buf) do { \
        const float* _x = xn + (size_t)(gch) * 32 * PD; \
        uint32_t _xd = smu + (unsigned)((wg * 2 + (buf)) * KA_XSF) * 4u; \
        _Pragma("unroll") \
        for (int i = 0; i < 8; i++) { \
            int idx = wtid + i * 128, c = idx >> 5, p4 = idx & 31; \
            CPA16(_xd + (unsigned)(c * 136 + p4 * 4) * 4u, _x + (size_t)c * PD + p4 * 4); \
        } \
        const float* _w = w + (gch) * 32; \
        uint32_t _wd = smu + (unsigned)(4 * KA_XSF + (wg * 2 + (buf)) * KA_WSF) * 4u; \
        _Pragma("unroll") \
        for (int i = 0; i < 2; i++) { \
            int idx = wtid + i * 128, k = idx >> 3, c4 = idx & 7; \
            CPA16(_wd + (unsigned)(k * 36 + c4 * 4) * 4u, _w + (size_t)k * CD + c4 * 4); \
        } \
        CPC(); \
    } while (0)

    KA_LD(wg * 16 + 0, 0);
    KA_LD(wg * 16 + 1, 1);

    for (int ch = 0; ch < 16; ch++) {
        const int buf = ch & 1;
        if (ch < 15) CPW1(); else CPW0();
        __syncthreads();
        const float* xsb = sm + (wg * 2 + buf) * KA_XSF;
        const float* wsb = sm + 4 * KA_XSF + (wg * 2 + buf) * KA_WSF;
#pragma unroll
        for (int c = 0; c < 32; c++) {
            float f = xsb[c * 136 + wtid];
            ssq = fmaf(f, f, ssq);
        }
#pragma unroll
        for (int s = 0; s < 4; s++) {
            uint32_t a[2][4], b[4][2];
            const int c0 = s * 8 + qlane;
#pragma unroll
            for (int mi = 0; mi < 2; mi++) {
                const int r0 = mi * 16 + qid;
                a[mi][0] = __float_as_uint(wsb[r0 * 36 + c0]);
                a[mi][1] = __float_as_uint(wsb[(r0 + 8) * 36 + c0]);
                a[mi][2] = __float_as_uint(wsb[r0 * 36 + c0 + 4]);
                a[mi][3] = __float_as_uint(wsb[(r0 + 8) * 36 + c0 + 4]);
            }
#pragma unroll
            for (int ni = 0; ni < 4; ni++) {
                const int pc = wp * 32 + ni * 8 + qid;
                b[ni][0] = __float_as_uint(xsb[c0 * 136 + pc]);
                b[ni][1] = __float_as_uint(xsb[(c0 + 4) * 136 + pc]);
            }
#pragma unroll
            for (int mi = 0; mi < 2; mi++)
#pragma unroll
                for (int ni = 0; ni < 4; ni++) mma8(d[mi][ni], a[mi], b[ni]);
        }
        __syncthreads();
        if (ch + 2 < 16) KA_LD(wg * 16 + ch + 2, buf);
    }
#undef KA_LD

    // ---- combine wg partial logits in smem: Ls[32 k][136] (aliases xs[0][0]) ----
    float (*Ls)[136] = (float (*)[136])sm;
    if (wg == 1) {
#pragma unroll
        for (int mi = 0; mi < 2; mi++)
#pragma unroll
            for (int ni = 0; ni < 4; ni++) {
                const int px = wp * 32 + ni * 8 + 2 * qlane;
                *(float2*)&Ls[mi * 16 + qid][px] = make_float2(d[mi][ni][0], d[mi][ni][1]);
                *(float2*)&Ls[mi * 16 + qid + 8][px] = make_float2(d[mi][ni][2], d[mi][ni][3]);
            }
        ssqs[wtid] = ssq;
    }
    __syncthreads();
    if (wg == 0) {
#pragma unroll
        for (int mi = 0; mi < 2; mi++)
#pragma unroll
            for (int ni = 0; ni < 4; ni++) {
                const int px = wp * 32 + ni * 8 + 2 * qlane;
                float2 u = *(float2*)&Ls[mi * 16 + qid][px];
                u.x += d[mi][ni][0]; u.y += d[mi][ni][1];
                *(float2*)&Ls[mi * 16 + qid][px] = u;
                float2 v = *(float2*)&Ls[mi * 16 + qid + 8][px];
                v.x += d[mi][ni][2]; v.y += d[mi][ni][3];
                *(float2*)&Ls[mi * 16 + qid + 8][px] = v;
            }
    }
    __syncthreads();

    // ---- softmax: wg0 thread owns pixel wtid ----
    if (wg == 0) {
        ssq += ssqs[wtid];
        const float r = 1.f / fmaxf(sqrtf(ssq), EPSN);
        float L[KC], m = -1e30f;
#pragma unroll
        for (int k = 0; k < KC; k++) {
            L[k] = Ls[k][wtid] * r;
            m = fmaxf(m, L[k]);
        }
        float ssum = 0.f;
#pragma unroll
        for (int k = 0; k < KC; k++) {
            L[k] = __expf(L[k] - m);
            ssum += L[k];
        }
        const float inv = 1.f / ssum;
        float* arp = g_ar + (size_t)n * KC * PD + pbase + wtid;
#pragma unroll
        for (int k = 0; k < KC; k++) {
            float a = L[k] * inv;
            arp[(size_t)k * PD] = a * r;
            float t = a;
            t += __shfl_xor_sync(0xffffffffu, t, 16);
            t += __shfl_xor_sync(0xffffffffu, t, 8);
            t += __shfl_xor_sync(0xffffffffu, t, 4);
            t += __shfl_xor_sync(0xffffffffu, t, 2);
            t += __shfl_xor_sync(0xffffffffu, t, 1);
            if (lane == 0) g_asp[(n * KC + k) * 32 + ptile * 4 + wp] = t;
        }
    }
}

// =====================================================================
// kb: vlad GEMM.  D[c=128, k=32] = sum_p x[c,p] * ar[k,p]
//   grid (8 ctiles, 16 n), 256 threads = 2 warpgroups.
//   wg0 reduces p[0..511], wg1 p[512..1023]; partial D combined in smem.
// =====================================================================
#define KB_XSF 4608              // 128*36 floats per buffer
#define KB_ASF 1152              // 32*36 floats per buffer
#define KB_SMEM ((4 * KB_XSF + 4 * KB_ASF) * 4)

__global__ void __launch_bounds__(256, 1) kb(const float* __restrict__ x) {
    extern __shared__ float sm[];
    const int tid = threadIdx.x;
    const int wg = tid >> 7, wtid = tid & 127;
    const int lane = tid & 31, wp = wtid >> 5;
    const int qid = lane >> 2, qlane = lane & 3;
    const int ctile = blockIdx.x, n = blockIdx.y, cbase = ctile * 128;
    const float* xn = x + ((size_t)n * CD + cbase) * PD;
    const float* arn = g_ar + (size_t)n * KC * PD;
    const uint32_t smu = s2u(sm);

    float d[2][4][4];
#pragma unroll
    for (int mi = 0; mi < 2; mi++)
#pragma unroll
        for (int ni = 0; ni < 4; ni++)
#pragma unroll
            for (int r = 0; r < 4; r++) d[mi][ni][r] = 0.f;

#define KB_LD(gch, buf) do { \
        const int _p0 = (gch) * 32; \
        uint32_t _xd = smu + (unsigned)((wg * 2 + (buf)) * KB_XSF) * 4u; \
        _Pragma("unroll") \
        for (int i = 0; i < 8; i++) { \
            int idx = wtid + i * 128, c = idx >> 3, p4 = idx & 7; \
            CPA16(_xd + (unsigned)(c * 36 + p4 * 4) * 4u, xn + (size_t)c * PD + _p0 + p4 * 4); \
        } \
        uint32_t _ad = smu + (unsigned)(4 * KB_XSF + (wg * 2 + (buf)) * KB_ASF) * 4u; \
        _Pragma("unroll") \
        for (int i = 0; i < 2; i++) { \
            int idx = wtid + i * 128, k = idx >> 3, p4 = idx & 7; \
            CPA16(_ad + (unsigned)(k * 36 + p4 * 4) * 4u, arn + (size_t)k * PD + _p0 + p4 * 4); \
        } \
        CPC(); \
    } while (0)

    KB_LD(wg * 16 + 0, 0);
    KB_LD(wg * 16 + 1, 1);

    for (int ch = 0; ch < 16; ch++) {
        const int buf = ch & 1;
        if (ch < 15) CPW1(); else CPW0();
        __syncthreads();
        const float* xsb = sm + (wg * 2 + buf) * KB_XSF;
        const float* asb = sm + 4 * KB_XSF + (wg * 2 + buf) * KB_ASF;
#pragma unroll
        for (int s = 0; s < 4; s++) {
            uint32_t a[2][4], b[4][2];
            const int p0 = s * 8 + qlane;
#pragma unroll
            for (int mi = 0; mi < 2; mi++) {
                const int r0 = wp * 32 + mi * 16 + qid;
                a[mi][0] = __float_as_uint(xsb[r0 * 36 + p0]);
                a[mi][1] = __float_as_uint(xsb[(r0 + 8) * 36 + p0]);
                a[mi][2] = __float_as_uint(xsb[r0 * 36 + p0 + 4]);
                a[mi][3] = __float_as_uint(xsb[(r0 + 8) * 36 + p0 + 4]);
            }
#pragma unroll
            for (int ni = 0; ni < 4; ni++) {
                const int kk = ni * 8 + qid;
                b[ni][0] = __float_as_uint(asb[kk * 36 + p0]);
                b[ni][1] = __float_as_uint(asb[kk * 36 + p0 + 4]);
            }
#pragma unroll
            for (int mi = 0; mi < 2; mi++)
#pragma unroll
                for (int ni = 0; ni < 4; ni++) mma8(d[mi][ni], a[mi], b[ni]);
        }
        __syncthreads();
        if (ch + 2 < 16) KB_LD(wg * 16 + ch + 2, buf);
    }
#undef KB_LD

    // ---- combine wg partial D in smem: Dsm[128 c][34] (aliases xs) ----
    float (*Dsm)[34] = (float (*)[34])sm;
    if (wg == 1) {
#pragma unroll
        for (int mi = 0; mi < 2; mi++) {
            const int cl = wp * 32 + mi * 16 + qid;
#pragma unroll
            for (int ni = 0; ni < 4; ni++) {
                const int k0 = ni * 8 + 2 * qlane;
                *(float2*)&Dsm[cl][k0] = make_float2(d[mi][ni][0], d[mi][ni][1]);
                *(float2*)&Dsm[cl + 8][k0] = make_float2(d[mi][ni][2], d[mi][ni][3]);
            }
        }
    }
    __syncthreads();
    if (wg == 0) {
        float* gv = g_v + (size_t)n * KC * CD;
#pragma unroll
        for (int mi = 0; mi < 2; mi++) {
            const int cl = wp * 32 + mi * 16 + qid;
            const int c0 = cbase + cl;
#pragma unroll
            for (int ni = 0; ni < 4; ni++) {
                const int k0 = ni * 8 + 2 * qlane;
                float2 u = *(float2*)&Dsm[cl][k0];
                float2 v = *(float2*)&Dsm[cl + 8][k0];
                gv[(size_t)k0 * CD + c0] = u.x + d[mi][ni][0];
                gv[(size_t)(k0 + 1) * CD + c0] = u.y + d[mi][ni][1];
                gv[(size_t)k0 * CD + c0 + 8] = v.x + d[mi][ni][2];
                gv[(size_t)(k0 + 1) * CD + c0 + 8] = v.y + d[mi][ni][3];
            }
        }
    }
}

// =====================================================================
// kc2: asum reduce + subtract asum*centroid + intra-cluster L2 norm.
//   grid 512 (row = n*32+k), 256 threads.
// =====================================================================
__global__ void __launch_bounds__(256) kc2(const float* __restrict__ cent,
                                           float* __restrict__ out) {
    const int row = blockIdx.x, k = row & 31;
    const int tid = threadIdx.x, lane = tid & 31, wp = tid >> 5;
    const int c = tid * 4;
    __shared__ float sasum, sh[8], sinv;

    if (tid < 32) {
        float t = g_asp[row * 32 + tid];
        t += __shfl_xor_sync(0xffffffffu, t, 16);
        t += __shfl_xor_sync(0xffffffffu, t, 8);
        t += __shfl_xor_sync(0xffffffffu, t, 4);
        t += __shfl_xor_sync(0xffffffffu, t, 2);
        t += __shfl_xor_sync(0xffffffffu, t, 1);
        if (tid == 0) sasum = t;
    }
    float4 v = *(const float4*)(g_v + (size_t)row * CD + c);
    float4 ce = *(const float4*)(cent + k * CD + c);
    __syncthreads();
    const float asum = sasum;
    v.x -= asum * ce.x; v.y -= asum * ce.y; v.z -= asum * ce.z; v.w -= asum * ce.w;
    float s = v.x * v.x + v.y * v.y + v.z * v.z + v.w * v.w;
    s += __shfl_xor_sync(0xffffffffu, s, 16);
    s += __shfl_xor_sync(0xffffffffu, s, 8);
    s += __shfl_xor_sync(0xffffffffu, s, 4);
    s += __shfl_xor_sync(0xffffffffu, s, 2);
    s += __shfl_xor_sync(0xffffffffu, s, 1);
    if (lane == 0) sh[wp] = s;
    __syncthreads();
    if (tid == 0) {
        float tot = 0.f;
#pragma unroll
        for (int i = 0; i < 8; i++) tot += sh[i];
        float inv = 1.f / fmaxf(sqrtf(tot), EPSN);
        sinv = inv;
        g_gg[row] = tot * inv * inv;
    }
    __syncthreads();
    const float inv = sinv;
    *(float4*)(out + (size_t)row * CD + c) =
        make_float4(v.x * inv, v.y * inv, v.z * inv, v.w * inv);
}

// kd: global L2 normalize. grid 512, 256 thr.
__global__ void __launch_bounds__(256) kd(float* __restrict__ out) {
    const int row = blockIdx.x, n = row >> 5, tid = threadIdx.x;
    __shared__ float sinv;
    if (tid < 32) {
        float v = g_gg[n * 32 + tid];
        v += __shfl_xor_sync(0xffffffffu, v, 16);
        v += __shfl_xor_sync(0xffffffffu, v, 8);
        v += __shfl_xor_sync(0xffffffffu, v, 4);
        v += __shfl_xor_sync(0xffffffffu, v, 2);
        v += __shfl_xor_sync(0xffffffffu, v, 1);
        if (tid == 0) sinv = 1.f / fmaxf(sqrtf(v), EPSN);
    }
    __syncthreads();
    const float inv = sinv;
    float4* p = (float4*)(out + (size_t)row * CD) + tid;
    float4 v = *p;
    *p = make_float4(v.x * inv, v.y * inv, v.z * inv, v.w * inv);
}

extern "C" void kernel_launch(void* const* d_in, const int* in_sizes, int n_in,
                              void* d_out, int out_size) {
    const float* x = (const float*)d_in[0];     // (16,1024,32,32)
    const float* w = (const float*)d_in[1];     // (32,1024)
    const float* cent = (const float*)d_in[2];  // (32,1024)
    float* out = (float*)d_out;                 // (16,32768)

    static int inited = 0;
    if (!inited) {
        cudaFuncSetAttribute(ka, cudaFuncAttributeMaxDynamicSharedMemorySize, KA_SMEM);
        cudaFuncSetAttribute(kb, cudaFuncAttributeMaxDynamicSharedMemorySize, KB_SMEM);
        inited = 1;
    }

    ka<<<dim3(8, 16), 256, KA_SMEM>>>(x, w);
    kb<<<dim3(8, 16), 256, KB_SMEM>>>(x);
    kc2<<<512, 256>>>(cent, out);
    kd<<<512, 256>>>(out);
}